// round 13
// baseline (speedup 1.0000x reference)
#include <cuda_runtime.h>

#define B_   32
#define T_   256
#define F_   64
#define C_   16
#define CO_  16
#define P_   64
#define S_   32
#define K_   4
#define FC   1024
#define KIN  1056
#define OUTC 96
#define ROWS (B_*T_)        // 8192
#define RSTR (F_*OUTC)      // 6144 floats per (b,t) row

// split-K8 partial sums (no bias/relu): 8 x 8192 x 64 fp32 = 16 MB
__device__ __align__(256) float g_part[8][ROWS][P_];

// ---------------- packed f32x2 helpers ----------------
__device__ __forceinline__ double pack2(float lo, float hi) {
    double d; asm("mov.b64 %0, {%1, %2};" : "=d"(d) : "f"(lo), "f"(hi)); return d;
}
__device__ __forceinline__ float2 unpack2(double d) {
    float2 v; asm("mov.b64 {%0, %1}, %2;" : "=f"(v.x), "=f"(v.y) : "d"(d)); return v;
}
__device__ __forceinline__ void fma2(double& acc, double a, double b) {
    asm("fma.rn.f32x2 %0, %1, %2, %3;" : "=d"(acc) : "d"(a), "d"(b), "d"(acc));
}

// ============================================================================
// Kernel 1: split-K8 point GEMM. grid=1024 (128 tiles x 8 octants), 128 thr.
// BM=64, BN=64, BK=32. Per-thread 4m x 8n: 4 LDS.128 : 16 FMA2 per kk.
// octant 0: kb [0,5); octant o>0: kb [4o+1, 4o+5).
// ============================================================================
__global__ __launch_bounds__(128)
void tpc_gemm(const float* __restrict__ x,
              const float* __restrict__ stat,
              const float* __restrict__ W_p)
{
    __shared__ __align__(16) double Ad[32][66];   // [kk][m] dup doubles (BM=64)
    __shared__ __align__(16) float  Bsf[32][64];  // [kk][n] natural pairs

    const int tid  = threadIdx.x;
    const int tile = blockIdx.x >> 3;             // 0..127
    const int oct  = blockIdx.x & 7;
    const int row0 = tile * 64;
    const int b    = row0 >> 8;

    const int kb0 = (oct == 0) ? 0 : (4 * oct + 1);
    const int kbE = 4 * oct + 5;

    const int m0 = (tid >> 3) * 4;                // 16 m-groups of 4
    const int n0 = (tid & 7) * 8;                 // 8 n-groups of 8 floats

    const int akq = tid & 7;                      // A loader: k-quad
    const int ar0 = tid >> 3;                     // A loader: row base (stride 16)
    const int bnq = tid & 15;                     // B loader: n-quad
    const int bk0 = tid >> 4;                     // B loader: kk base (stride 8)

    double acc[4][4];                             // [m][n-pair]
    #pragma unroll
    for (int i = 0; i < 4; ++i)
        #pragma unroll
        for (int j = 0; j < 4; ++j) acc[i][j] = 0.0;

    float4 pa[4], pb[4];

    // prefetch first tile (kb0 <= 29 -> k < 1024, x only)
    #pragma unroll
    for (int l = 0; l < 4; ++l) {
        int r = ar0 + l * 16;
        pa[l] = *reinterpret_cast<const float4*>(
            &x[(size_t)(row0 + r) * FC + kb0 * 32 + akq * 4]);
    }
    #pragma unroll
    for (int l = 0; l < 4; ++l) {
        int kk = bk0 + l * 8;
        pb[l] = *reinterpret_cast<const float4*>(
            &W_p[(size_t)(kb0 * 32 + kk) * P_ + bnq * 4]);
    }

    for (int kb = kb0; kb < kbE; ++kb) {
        // commit prefetched tiles
        #pragma unroll
        for (int l = 0; l < 4; ++l) {
            int r = ar0 + l * 16;
            Ad[akq * 4 + 0][r] = pack2(pa[l].x, pa[l].x);
            Ad[akq * 4 + 1][r] = pack2(pa[l].y, pa[l].y);
            Ad[akq * 4 + 2][r] = pack2(pa[l].z, pa[l].z);
            Ad[akq * 4 + 3][r] = pack2(pa[l].w, pa[l].w);
        }
        #pragma unroll
        for (int l = 0; l < 4; ++l) {
            int kk = bk0 + l * 8;
            *reinterpret_cast<float4*>(&Bsf[kk][bnq * 4]) = pb[l];
        }
        __syncthreads();

        // prefetch next tile during compute
        if (kb + 1 < kbE) {
            int kg0 = (kb + 1) * 32;
            #pragma unroll
            for (int l = 0; l < 4; ++l) {
                int r   = ar0 + l * 16;
                int kgf = kg0 + akq * 4;
                if (kgf < FC)
                    pa[l] = *reinterpret_cast<const float4*>(&x[(size_t)(row0 + r) * FC + kgf]);
                else
                    pa[l] = *reinterpret_cast<const float4*>(&stat[b * S_ + (kgf - FC)]);
            }
            #pragma unroll
            for (int l = 0; l < 4; ++l) {
                int kk = bk0 + l * 8;
                pb[l] = *reinterpret_cast<const float4*>(
                    &W_p[(size_t)(kg0 + kk) * P_ + bnq * 4]);
            }
        }

        #pragma unroll
        for (int kk = 0; kk < 32; ++kk) {
            double2 a01 = *reinterpret_cast<const double2*>(&Ad[kk][m0]);
            double2 a23 = *reinterpret_cast<const double2*>(&Ad[kk][m0 + 2]);
            double2 b01 = *reinterpret_cast<const double2*>(&Bsf[kk][n0]);
            double2 b23 = *reinterpret_cast<const double2*>(&Bsf[kk][n0 + 4]);
            fma2(acc[0][0], a01.x, b01.x); fma2(acc[0][1], a01.x, b01.y);
            fma2(acc[0][2], a01.x, b23.x); fma2(acc[0][3], a01.x, b23.y);
            fma2(acc[1][0], a01.y, b01.x); fma2(acc[1][1], a01.y, b01.y);
            fma2(acc[1][2], a01.y, b23.x); fma2(acc[1][3], a01.y, b23.y);
            fma2(acc[2][0], a23.x, b01.x); fma2(acc[2][1], a23.x, b01.y);
            fma2(acc[2][2], a23.x, b23.x); fma2(acc[2][3], a23.x, b23.y);
            fma2(acc[3][0], a23.y, b01.x); fma2(acc[3][1], a23.y, b01.y);
            fma2(acc[3][2], a23.y, b23.x); fma2(acc[3][3], a23.y, b23.y);
        }
        __syncthreads();
    }

    // store raw partials: 4 rows x 8 floats per thread
    #pragma unroll
    for (int m = 0; m < 4; ++m) {
        float2 p0 = unpack2(acc[m][0]);
        float2 p1 = unpack2(acc[m][1]);
        float2 p2 = unpack2(acc[m][2]);
        float2 p3 = unpack2(acc[m][3]);
        int row = row0 + m0 + m;
        *reinterpret_cast<float4*>(&g_part[oct][row][n0]) =
            make_float4(p0.x, p0.y, p1.x, p1.y);
        *reinterpret_cast<float4*>(&g_part[oct][row][n0 + 4]) =
            make_float4(p2.x, p2.y, p3.x, p3.y);
    }
}

// ============================================================================
// Kernel 2: interleaved roles (R12 kernel, measured 53.4us; only change:
// stream role sums 8 partials). even blocks: conv -> ch16..31.
// odd blocks: relu(x) ch0..15 + sum partials + bias + relu -> ch32..95.
// ============================================================================
__global__ __launch_bounds__(256, 4)
void tpc_fuse(const float* __restrict__ x,
              const float* __restrict__ conv_w,
              const float* __restrict__ conv_b,
              const float* __restrict__ b_p,
              float* __restrict__ out)
{
    __shared__ __align__(16) float xs[T_ + 6][17];
    __shared__ __align__(16) float ws[64][20];
    __shared__ float bsv[16];

    const int tid = threadIdx.x;

    if ((blockIdx.x & 1) == 0) {
        // ---------------- CONV ROLE ----------------
        const int cb = blockIdx.x >> 1;
        const int b  = cb >> 6;
        const int f  = cb & 63;
        const size_t xrow0 = ((size_t)b * T_ * F_ + f) * C_;

        #pragma unroll
        for (int l = 0; l < 5; ++l) {
            int idx = tid + l * 256;
            if (idx < (T_ + 6) * 4) {
                int r = idx >> 2;
                int q = idx & 3;
                float4 v = make_float4(0.f, 0.f, 0.f, 0.f);
                if (r >= 6)
                    v = *reinterpret_cast<const float4*>(&x[xrow0 + (size_t)(r - 6) * FC + q * 4]);
                xs[r][q * 4 + 0] = v.x;
                xs[r][q * 4 + 1] = v.y;
                xs[r][q * 4 + 2] = v.z;
                xs[r][q * 4 + 3] = v.w;
            }
        }
        {
            int co = tid >> 4;
            int c  = tid & 15;
            float4 w = *reinterpret_cast<const float4*>(&conv_w[((size_t)f * CO_ + co) * 64 + c * 4]);
            ws[c * 4 + 0][co] = w.x;
            ws[c * 4 + 1][co] = w.y;
            ws[c * 4 + 2][co] = w.z;
            ws[c * 4 + 3][co] = w.w;
        }
        if (tid < 16) bsv[tid] = conv_b[f * CO_ + tid];
        __syncthreads();

        const int t0  = (tid >> 2) * 4;
        const int co0 = (tid & 3) * 4;

        double acc[4][2];
        #pragma unroll
        for (int i = 0; i < 4; ++i) { acc[i][0] = 0.0; acc[i][1] = 0.0; }

        #pragma unroll 4
        for (int c = 0; c < C_; ++c) {
            double ad[10];
            #pragma unroll
            for (int r = 0; r < 10; ++r) {
                float a = xs[t0 + r][c];
                ad[r] = pack2(a, a);
            }
            #pragma unroll
            for (int k = 0; k < K_; ++k) {
                double2 w = *reinterpret_cast<const double2*>(&ws[c * 4 + k][co0]);
                #pragma unroll
                for (int i = 0; i < 4; ++i) {
                    fma2(acc[i][0], ad[i + 2 * k], w.x);
                    fma2(acc[i][1], ad[i + 2 * k], w.y);
                }
            }
        }

        float4 bb = *reinterpret_cast<const float4*>(&bsv[co0]);
        float* ob = out + ((size_t)b * T_ * F_ + f) * OUTC;
        #pragma unroll
        for (int i = 0; i < 4; ++i) {
            float2 q0 = unpack2(acc[i][0]);
            float2 q1 = unpack2(acc[i][1]);
            float4 v = make_float4(fmaxf(q0.x + bb.x, 0.f), fmaxf(q0.y + bb.y, 0.f),
                                   fmaxf(q1.x + bb.z, 0.f), fmaxf(q1.y + bb.w, 0.f));
            *reinterpret_cast<float4*>(&ob[(size_t)(t0 + i) * RSTR + 16 + co0]) = v;
        }
    } else {
        // ---------------- STREAM ROLE ----------------
        const int rb = blockIdx.x >> 1;
        const int row_base = rb * 4;

        // ch 0..15: relu(x) (1024 float4)
        #pragma unroll
        for (int l = 0; l < 4; ++l) {
            int idx  = tid + l * 256;
            int r    = idx >> 8;
            int rest = idx & 255;
            int row  = row_base + r;
            float4 v = *reinterpret_cast<const float4*>(&x[(size_t)row * FC + rest * 4]);
            v.x = fmaxf(v.x, 0.f); v.y = fmaxf(v.y, 0.f);
            v.z = fmaxf(v.z, 0.f); v.w = fmaxf(v.w, 0.f);
            int f = rest >> 2;
            int q = rest & 3;
            *reinterpret_cast<float4*>(&out[(size_t)row * RSTR + f * OUTC + q * 4]) = v;
        }
        // ch 32..95: sum 8 K-partials + bias + relu, broadcast (4096 float4)
        const int q  = tid & 15;
        const int f0 = tid >> 4;
        float4 bb = *reinterpret_cast<const float4*>(&b_p[q * 4]);
        #pragma unroll
        for (int rr = 0; rr < 4; ++rr) {
            int row = row_base + rr;
            float4 s = bb;
            #pragma unroll
            for (int o = 0; o < 8; ++o) {
                float4 v = *reinterpret_cast<const float4*>(&g_part[o][row][q * 4]);
                s.x += v.x; s.y += v.y; s.z += v.z; s.w += v.w;
            }
            float4 v = make_float4(fmaxf(s.x, 0.f), fmaxf(s.y, 0.f),
                                   fmaxf(s.z, 0.f), fmaxf(s.w, 0.f));
            float* ob = out + (size_t)row * RSTR + 32 + q * 4;
            #pragma unroll
            for (int ff = 0; ff < 4; ++ff) {
                int f = ff * 16 + f0;
                *reinterpret_cast<float4*>(&ob[(size_t)f * OUTC]) = v;
            }
        }
    }
}

extern "C" void kernel_launch(void* const* d_in, const int* in_sizes, int n_in,
                              void* d_out, int out_size)
{
    const float* x      = (const float*)d_in[0];   // [32,256,64,16]
    const float* statv  = (const float*)d_in[1];   // [32,32]
    const float* conv_w = (const float*)d_in[2];   // [64,16,16,4]
    const float* conv_b = (const float*)d_in[3];   // [64,16]
    const float* W_p    = (const float*)d_in[4];   // [1056,64]
    const float* b_p    = (const float*)d_in[5];   // [64]
    float* out = (float*)d_out;                    // [32,256,64,96]

    tpc_gemm<<<1024, 128>>>(x, statv, W_p);
    tpc_fuse<<<4096, 256>>>(x, conv_w, conv_b, b_p, out);
}

// round 14
// speedup vs baseline: 1.1586x; 1.1586x over previous
#include <cuda_runtime.h>

#define B_   32
#define T_   256
#define F_   64
#define C_   16
#define CO_  16
#define P_   64
#define S_   32
#define K_   4
#define FC   1024
#define KIN  1056
#define OUTC 96
#define ROWS (B_*T_)        // 8192
#define RSTR (F_*OUTC)      // 6144 floats per (b,t) row

// split-K4 partial sums (no bias/relu): 4 x 8192 x 64 fp32 = 8 MB
__device__ __align__(256) float g_part[4][ROWS][P_];

// ---------------- packed f32x2 helpers ----------------
__device__ __forceinline__ double pack2(float lo, float hi) {
    double d; asm("mov.b64 %0, {%1, %2};" : "=d"(d) : "f"(lo), "f"(hi)); return d;
}
__device__ __forceinline__ float2 unpack2(double d) {
    float2 v; asm("mov.b64 {%0, %1}, %2;" : "=f"(v.x), "=f"(v.y) : "d"(d)); return v;
}
__device__ __forceinline__ void fma2(double& acc, double a, double b) {
    asm("fma.rn.f32x2 %0, %1, %2, %3;" : "=d"(acc) : "d"(a), "d"(b), "d"(acc));
}

// ============================================================================
// K1 (primary): split-K4 point GEMM. grid=1024 (256 tiles x 4 quarters),
// 128 thr. BM=32, BN=64, BK=32, per-thread 4m x 4n (conflict-free LDS).
// Triggers PDL completion at entry so tpc_conv overlaps.
// ============================================================================
__global__ __launch_bounds__(128)
void tpc_gemm(const float* __restrict__ x,
              const float* __restrict__ stat,
              const float* __restrict__ W_p)
{
    cudaTriggerProgrammaticLaunchCompletion();

    __shared__ __align__(16) double Ad[32][34];   // [kk][m] dup doubles
    __shared__ __align__(16) float  Bsf[32][64];  // [kk][n] natural pairs

    const int tid     = threadIdx.x;
    const int tile    = blockIdx.x >> 2;
    const int quarter = blockIdx.x & 3;
    const int row0    = tile * 32;
    const int b       = row0 >> 8;

    const int kb0 = (quarter == 0) ? 0 : (9 + 8 * (quarter - 1));   // {0,9,17,25}
    const int kbE = 9 + 8 * quarter;                                 // {9,17,25,33}

    const int m0  = (tid >> 4) * 4;
    const int n0  = (tid & 15) * 4;
    const int akq = tid & 7;

    double acc[4][2];
    #pragma unroll
    for (int i = 0; i < 4; ++i) { acc[i][0] = 0.0; acc[i][1] = 0.0; }

    float4 pa[2], pb[4];

    // prefetch first tile (kb0*32 + 31 < 1024 for all quarters -> x only)
    #pragma unroll
    for (int l = 0; l < 2; ++l) {
        int idx = tid + l * 128;
        int r   = idx >> 3;
        pa[l] = *reinterpret_cast<const float4*>(
            &x[(size_t)(row0 + r) * FC + kb0 * 32 + akq * 4]);
    }
    #pragma unroll
    for (int l = 0; l < 4; ++l) {
        int idx = tid + l * 128;
        pb[l] = *reinterpret_cast<const float4*>(
            &W_p[(size_t)(kb0 * 32 + (idx >> 4)) * P_ + (idx & 15) * 4]);
    }

    for (int kb = kb0; kb < kbE; ++kb) {
        #pragma unroll
        for (int l = 0; l < 2; ++l) {
            int idx = tid + l * 128;
            int r   = idx >> 3;
            Ad[akq * 4 + 0][r] = pack2(pa[l].x, pa[l].x);
            Ad[akq * 4 + 1][r] = pack2(pa[l].y, pa[l].y);
            Ad[akq * 4 + 2][r] = pack2(pa[l].z, pa[l].z);
            Ad[akq * 4 + 3][r] = pack2(pa[l].w, pa[l].w);
        }
        #pragma unroll
        for (int l = 0; l < 4; ++l) {
            int idx = tid + l * 128;
            *reinterpret_cast<float4*>(&Bsf[idx >> 4][(idx & 15) * 4]) = pb[l];
        }
        __syncthreads();

        if (kb + 1 < kbE) {
            int kg0 = (kb + 1) * 32;
            #pragma unroll
            for (int l = 0; l < 2; ++l) {
                int idx = tid + l * 128;
                int r   = idx >> 3;
                int kgf = kg0 + akq * 4;
                if (kgf < FC)
                    pa[l] = *reinterpret_cast<const float4*>(&x[(size_t)(row0 + r) * FC + kgf]);
                else
                    pa[l] = *reinterpret_cast<const float4*>(&stat[b * S_ + (kgf - FC)]);
            }
            #pragma unroll
            for (int l = 0; l < 4; ++l) {
                int idx = tid + l * 128;
                pb[l] = *reinterpret_cast<const float4*>(
                    &W_p[(size_t)(kg0 + (idx >> 4)) * P_ + (idx & 15) * 4]);
            }
        }

        #pragma unroll
        for (int kk = 0; kk < 32; ++kk) {
            double2 a01 = *reinterpret_cast<const double2*>(&Ad[kk][m0]);
            double2 a23 = *reinterpret_cast<const double2*>(&Ad[kk][m0 + 2]);
            double2 bp  = *reinterpret_cast<const double2*>(&Bsf[kk][n0]);
            fma2(acc[0][0], a01.x, bp.x); fma2(acc[0][1], a01.x, bp.y);
            fma2(acc[1][0], a01.y, bp.x); fma2(acc[1][1], a01.y, bp.y);
            fma2(acc[2][0], a23.x, bp.x); fma2(acc[2][1], a23.x, bp.y);
            fma2(acc[3][0], a23.y, bp.x); fma2(acc[3][1], a23.y, bp.y);
        }
        __syncthreads();
    }

    #pragma unroll
    for (int m = 0; m < 4; ++m) {
        float2 p = unpack2(acc[m][0]);
        float2 q = unpack2(acc[m][1]);
        *reinterpret_cast<float4*>(&g_part[quarter][row0 + m0 + m][n0]) =
            make_float4(p.x, p.y, q.x, q.y);
    }
}

// ============================================================================
// K2 (PDL secondary, fully independent of K1): conv per (b,f).
// Writes ch16..31 (conv+bias+relu) and ch0..15 (relu x). 2048 blocks.
// ============================================================================
__global__ __launch_bounds__(256, 4)
void tpc_conv(const float* __restrict__ x,
              const float* __restrict__ conv_w,
              const float* __restrict__ conv_b,
              float* __restrict__ out)
{
    __shared__ __align__(16) float xs[T_ + 6][17];
    __shared__ __align__(16) float ws[64][20];
    __shared__ float bsv[16];

    const int tid = threadIdx.x;
    const int b   = blockIdx.x >> 6;
    const int f   = blockIdx.x & 63;
    const size_t xrow0 = ((size_t)b * T_ * F_ + f) * C_;

    #pragma unroll
    for (int l = 0; l < 5; ++l) {
        int idx = tid + l * 256;
        if (idx < (T_ + 6) * 4) {
            int r = idx >> 2;
            int q = idx & 3;
            float4 v = make_float4(0.f, 0.f, 0.f, 0.f);
            if (r >= 6)
                v = *reinterpret_cast<const float4*>(&x[xrow0 + (size_t)(r - 6) * FC + q * 4]);
            xs[r][q * 4 + 0] = v.x;
            xs[r][q * 4 + 1] = v.y;
            xs[r][q * 4 + 2] = v.z;
            xs[r][q * 4 + 3] = v.w;
        }
    }
    {
        int co = tid >> 4;
        int c  = tid & 15;
        float4 w = *reinterpret_cast<const float4*>(&conv_w[((size_t)f * CO_ + co) * 64 + c * 4]);
        ws[c * 4 + 0][co] = w.x;
        ws[c * 4 + 1][co] = w.y;
        ws[c * 4 + 2][co] = w.z;
        ws[c * 4 + 3][co] = w.w;
    }
    if (tid < 16) bsv[tid] = conv_b[f * CO_ + tid];
    __syncthreads();

    const int t0  = (tid >> 2) * 4;
    const int co0 = (tid & 3) * 4;

    double acc[4][2];
    #pragma unroll
    for (int i = 0; i < 4; ++i) { acc[i][0] = 0.0; acc[i][1] = 0.0; }

    #pragma unroll 4
    for (int c = 0; c < C_; ++c) {
        double ad[10];
        #pragma unroll
        for (int r = 0; r < 10; ++r) {
            float a = xs[t0 + r][c];
            ad[r] = pack2(a, a);
        }
        #pragma unroll
        for (int k = 0; k < K_; ++k) {
            double2 w = *reinterpret_cast<const double2*>(&ws[c * 4 + k][co0]);
            #pragma unroll
            for (int i = 0; i < 4; ++i) {
                fma2(acc[i][0], ad[i + 2 * k], w.x);
                fma2(acc[i][1], ad[i + 2 * k], w.y);
            }
        }
    }

    float* ob = out + ((size_t)b * T_ * F_ + f) * OUTC;

    // ch16..31 from registers
    {
        float4 bb = *reinterpret_cast<const float4*>(&bsv[co0]);
        #pragma unroll
        for (int i = 0; i < 4; ++i) {
            float2 q0 = unpack2(acc[i][0]);
            float2 q1 = unpack2(acc[i][1]);
            float4 v = make_float4(fmaxf(q0.x + bb.x, 0.f), fmaxf(q0.y + bb.y, 0.f),
                                   fmaxf(q1.x + bb.z, 0.f), fmaxf(q1.y + bb.w, 0.f));
            *reinterpret_cast<float4*>(&ob[(size_t)(t0 + i) * RSTR + 16 + co0]) = v;
        }
    }

    // ch0..15 = relu(x) (L2-hot re-read, 1024 float4)
    #pragma unroll
    for (int l = 0; l < 4; ++l) {
        int idx = tid + l * 256;
        int t   = idx >> 2;
        int q   = idx & 3;
        float4 v = *reinterpret_cast<const float4*>(&x[xrow0 + (size_t)t * FC + q * 4]);
        v.x = fmaxf(v.x, 0.f); v.y = fmaxf(v.y, 0.f);
        v.z = fmaxf(v.z, 0.f); v.w = fmaxf(v.w, 0.f);
        *reinterpret_cast<float4*>(&ob[(size_t)t * RSTR + q * 4]) = v;
    }
}

// ============================================================================
// K3: broadcast. ch32..95 = relu(sum 4 partials + b_p) replicated across 64 f.
// Normal launch: stream order guarantees K1 and K2 are complete.
// ============================================================================
__global__ __launch_bounds__(256)
void tpc_bcast(const float* __restrict__ b_p, float* __restrict__ out)
{
    const int tid = threadIdx.x;
    const int q   = tid & 15;
    const int f0  = tid >> 4;
    const int row_base = blockIdx.x * 4;
    float4 bb = *reinterpret_cast<const float4*>(&b_p[q * 4]);

    #pragma unroll
    for (int rr = 0; rr < 4; ++rr) {
        int row = row_base + rr;
        float4 v0 = *reinterpret_cast<const float4*>(&g_part[0][row][q * 4]);
        float4 v1 = *reinterpret_cast<const float4*>(&g_part[1][row][q * 4]);
        float4 v2 = *reinterpret_cast<const float4*>(&g_part[2][row][q * 4]);
        float4 v3 = *reinterpret_cast<const float4*>(&g_part[3][row][q * 4]);
        float4 v;
        v.x = fmaxf((v0.x + v1.x) + (v2.x + v3.x) + bb.x, 0.f);
        v.y = fmaxf((v0.y + v1.y) + (v2.y + v3.y) + bb.y, 0.f);
        v.z = fmaxf((v0.z + v1.z) + (v2.z + v3.z) + bb.z, 0.f);
        v.w = fmaxf((v0.w + v1.w) + (v2.w + v3.w) + bb.w, 0.f);
        float* ob = out + (size_t)row * RSTR + 32 + q * 4;
        #pragma unroll
        for (int ff = 0; ff < 4; ++ff) {
            int f = ff * 16 + f0;
            *reinterpret_cast<float4*>(&ob[(size_t)f * OUTC]) = v;
        }
    }
}

extern "C" void kernel_launch(void* const* d_in, const int* in_sizes, int n_in,
                              void* d_out, int out_size)
{
    const float* x      = (const float*)d_in[0];   // [32,256,64,16]
    const float* statv  = (const float*)d_in[1];   // [32,32]
    const float* conv_w = (const float*)d_in[2];   // [64,16,16,4]
    const float* conv_b = (const float*)d_in[3];   // [64,16]
    const float* W_p    = (const float*)d_in[4];   // [1056,64]
    const float* b_p    = (const float*)d_in[5];   // [64]
    float* out = (float*)d_out;                    // [32,256,64,96]

    // K1: GEMM primary, triggers PDL completion at entry
    tpc_gemm<<<1024, 128>>>(x, statv, W_p);

    // K2: conv, PDL secondary — overlaps K1 (no dependency, no spinning)
    {
        cudaLaunchConfig_t cfg = {};
        cfg.gridDim  = dim3(2048);
        cfg.blockDim = dim3(256);
        cfg.dynamicSmemBytes = 0;
        cfg.stream = 0;
        cudaLaunchAttribute attrs[1];
        attrs[0].id = cudaLaunchAttributeProgrammaticStreamSerialization;
        attrs[0].val.programmaticStreamSerializationAllowed = 1;
        cfg.attrs = attrs;
        cfg.numAttrs = 1;
        cudaLaunchKernelEx(&cfg, tpc_conv, x, conv_w, conv_b, (float*)d_out);
    }

    // K3: broadcast — normal launch, waits for K1+K2 via stream order
    tpc_bcast<<<ROWS / 4, 256>>>(b_p, out);
}